// round 7
// baseline (speedup 1.0000x reference)
#include <cuda_runtime.h>
#include <cstdint>

// SoftCountPixels: Y[b,p] = (1/(H*W)) * sum_{h,w} exp(-||x[b,:,h,w] - P[p,:]||_2 / 0.6)
// x: (16, 3, 256, 256) f32 planar; P: (32, 3) f32; out: (16, 32) f32
//
// exp(-d/0.6) = ex2(-sqrt(K2*d^2)), K2=(log2e/0.6)^2: pre-scaled quadratic form,
// |.| / neg fold into MUFU source modifiers; packed f32x2 pair math.
//
// R7 KEY CHANGE: perfectly balanced flat work partition. Instead of a
// (chunk, b, pg) grid (384 blocks -> 88 SMs with 3 CTAs, 60 with 2 -> 86.5%
// ceiling), launch exactly 444 = 148*3 blocks and split the global unit space
// (128 combos x 16384 vec4 = 2,097,152 units) into 444 equal contiguous
// ranges. A range crosses at most one combo boundary -> <=2 uniform segments
// per block, each with its own proto constants and its own flush.

#define B 16
#define HW (256 * 256)
#define HW4 (HW / 4)             // 16384 = 2^14 vec4 per channel plane
#define HW4_SHIFT 14
#define NPRO 32
#define PPT 4                    // protos per thread
#define PGROUPS (NPRO / PPT)     // 8
#define NCOMBO (B * PGROUPS)     // 128
#define THREADS 256
#define NBLOCKS 444              // 148 SMs * 3 CTAs -> one perfectly balanced wave
#define TOTAL_UNITS ((unsigned long long)NCOMBO * HW4)   // 2,097,152

#define K2 5.781580510735007f    // (log2(e)/0.6)^2

__device__ __forceinline__ float fast_sqrt(float v) {
    float r;
    asm("sqrt.approx.f32 %0, %1;" : "=f"(r) : "f"(v));
    return r;
}
__device__ __forceinline__ float fast_ex2(float v) {
    float r;
    asm("ex2.approx.f32 %0, %1;" : "=f"(r) : "f"(v));
    return r;
}

// ---- packed f32x2 helpers ----
__device__ __forceinline__ uint64_t pack2(float lo, float hi) {
    uint64_t r;
    asm("mov.b64 %0, {%1, %2};" : "=l"(r) : "f"(lo), "f"(hi));
    return r;
}
__device__ __forceinline__ void unpack2(uint64_t v, float& lo, float& hi) {
    asm("mov.b64 {%0, %1}, %2;" : "=f"(lo), "=f"(hi) : "l"(v));
}
__device__ __forceinline__ uint64_t fma2(uint64_t a, uint64_t b, uint64_t c) {
    uint64_t r;
    asm("fma.rn.f32x2 %0, %1, %2, %3;" : "=l"(r) : "l"(a), "l"(b), "l"(c));
    return r;
}
__device__ __forceinline__ uint64_t add2(uint64_t a, uint64_t b) {
    uint64_t r;
    asm("add.rn.f32x2 %0, %1, %2;" : "=l"(r) : "l"(a), "l"(b));
    return r;
}
__device__ __forceinline__ uint64_t mul2(uint64_t a, uint64_t b) {
    uint64_t r;
    asm("mul.rn.f32x2 %0, %1, %2;" : "=l"(r) : "l"(a), "l"(b));
    return r;
}

__global__ void zero_out_kernel(float* out, int n) {
    int i = blockIdx.x * blockDim.x + threadIdx.x;
    if (i < n) out[i] = 0.0f;
}

__global__ __launch_bounds__(THREADS, 3)
void softcount_kernel(const float* __restrict__ x,
                      const float* __restrict__ P,
                      float* __restrict__ out) {
    const int tid  = threadIdx.x;
    const int lane = tid & 31;
    const unsigned long long bid = blockIdx.x;

    // This block's contiguous range of global vec4-units.
    unsigned long long u0 = (bid * TOTAL_UNITS) / NBLOCKS;
    const unsigned long long u1 = ((bid + 1) * TOTAL_UNITS) / NBLOCKS;

    while (u0 < u1) {
        const unsigned combo = (unsigned)(u0 >> HW4_SHIFT);         // 0..127
        const unsigned long long combo_end = (unsigned long long)(combo + 1) << HW4_SHIFT;
        const unsigned long long seg_end = (u1 < combo_end) ? u1 : combo_end;

        const int pg = (int)(combo >> 4);   // 0..7
        const int b  = (int)(combo & 15);   // 0..15

        // Packed (broadcast) per-proto constants, pre-scaled by K2.
        uint64_t qk0[PPT], qk1[PPT], qk2[PPT], cck[PPT];
        float acc[PPT];
#pragma unroll
        for (int i = 0; i < PPT; i++) {
            const int p = pg * PPT + i;
            const float p0 = __ldg(&P[p * 3 + 0]);
            const float p1 = __ldg(&P[p * 3 + 1]);
            const float p2 = __ldg(&P[p * 3 + 2]);
            const float q0 = -2.0f * K2 * p0;
            const float q1 = -2.0f * K2 * p1;
            const float q2 = -2.0f * K2 * p2;
            const float cc = K2 * (p0 * p0 + p1 * p1 + p2 * p2);
            qk0[i] = pack2(q0, q0);
            qk1[i] = pack2(q1, q1);
            qk2[i] = pack2(q2, q2);
            cck[i] = pack2(cc, cc);
            acc[i] = 0.0f;
        }
        const uint64_t K2_2 = pack2(K2, K2);

        // Local vec4 index range within this combo's image.
        const int vs = (int)(u0 & (HW4 - 1));
        const int ve = (int)(seg_end - ((unsigned long long)combo << HW4_SHIFT));

        const ulonglong2* xb = (const ulonglong2*)(x + (size_t)b * 3 * HW);

        for (int v = vs + tid; v < ve; v += THREADS) {
            const ulonglong2 c0 = xb[v];              // ch0: pixels(0,1),(2,3) packed
            const ulonglong2 c1 = xb[v + HW4];        // ch1
            const ulonglong2 c2 = xb[v + 2 * HW4];    // ch2

            // ---- pixel pair (0,1) ----
            {
                const uint64_t X0 = c0.x, X1 = c1.x, X2 = c2.x;
                uint64_t xx = mul2(X0, X0);
                xx = fma2(X1, X1, xx);
                xx = fma2(X2, X2, xx);
                const uint64_t xxk = mul2(K2_2, xx);
#pragma unroll
                for (int i = 0; i < PPT; i++) {
                    uint64_t t = add2(cck[i], xxk);
                    t = fma2(qk0[i], X0, t);
                    t = fma2(qk1[i], X1, t);
                    t = fma2(qk2[i], X2, t);
                    float ta, tb;
                    unpack2(t, ta, tb);
                    acc[i] += fast_ex2(-fast_sqrt(fabsf(ta)));
                    acc[i] += fast_ex2(-fast_sqrt(fabsf(tb)));
                }
            }
            // ---- pixel pair (2,3) ----
            {
                const uint64_t X0 = c0.y, X1 = c1.y, X2 = c2.y;
                uint64_t xx = mul2(X0, X0);
                xx = fma2(X1, X1, xx);
                xx = fma2(X2, X2, xx);
                const uint64_t xxk = mul2(K2_2, xx);
#pragma unroll
                for (int i = 0; i < PPT; i++) {
                    uint64_t t = add2(cck[i], xxk);
                    t = fma2(qk0[i], X0, t);
                    t = fma2(qk1[i], X1, t);
                    t = fma2(qk2[i], X2, t);
                    float ta, tb;
                    unpack2(t, ta, tb);
                    acc[i] += fast_ex2(-fast_sqrt(fabsf(ta)));
                    acc[i] += fast_ex2(-fast_sqrt(fabsf(tb)));
                }
            }
        }

        // Flush this segment: warp shuffle reduce, one global atomic per
        // (warp, proto). 444 blocks * <=2 segs * 8 warps * 4 atomics onto
        // 512 addresses — negligible.
#pragma unroll
        for (int i = 0; i < PPT; i++) {
            float v = acc[i];
#pragma unroll
            for (int off = 16; off > 0; off >>= 1)
                v += __shfl_xor_sync(0xFFFFFFFFu, v, off);
            if (lane == 0)
                atomicAdd(&out[b * NPRO + pg * PPT + i], v * (1.0f / (float)HW));
        }

        u0 = seg_end;
    }
}

extern "C" void kernel_launch(void* const* d_in, const int* in_sizes, int n_in,
                              void* d_out, int out_size) {
    const float* x = (const float*)d_in[0];
    const float* P = (const float*)d_in[1];
    float* out = (float*)d_out;

    zero_out_kernel<<<(out_size + 255) / 256, 256>>>(out, out_size);
    softcount_kernel<<<NBLOCKS, THREADS>>>(x, P, out);
}